// round 8
// baseline (speedup 1.0000x reference)
#include <cuda_runtime.h>
#include <cuda_bf16.h>
#include <cstdint>

#define OUT_F 4096
#define IN_F  4096
#define TOKENS 8192

// Static device scratch (allowed): dequantized W (32 MB) + x as bf16 (64 MB)
__device__ __align__(16) __nv_bfloat16 g_W[(size_t)OUT_F * IN_F];
__device__ __align__(16) __nv_bfloat16 g_X[(size_t)TOKENS * IN_F];

// ---------------------------------------------------------------------------
// Kernel 1: NF4 dequant -> bf16.  Each thread: 4 packed int32 = 8 weights.
// low nibble -> even element, high nibble -> odd; scale block = elem/64.
// (Validated byte-level in R7 diagnostics.)
// ---------------------------------------------------------------------------
__global__ void nf4_dequant_kernel(const int* __restrict__ pw,
                                   const float* __restrict__ scales,
                                   const float* __restrict__ table) {
    __shared__ float t[16];
    if (threadIdx.x < 16) t[threadIdx.x] = table[threadIdx.x];
    __syncthreads();

    int gid = blockIdx.x * blockDim.x + threadIdx.x;   // 2,097,152 threads
    int4 p = reinterpret_cast<const int4*>(pw)[gid];
    float s = scales[gid >> 3];

    int v[4] = {p.x, p.y, p.z, p.w};
    union { __nv_bfloat16 h[8]; uint4 vec; } o;
#pragma unroll
    for (int j = 0; j < 4; ++j) {
        o.h[2 * j]     = __float2bfloat16(t[v[j] & 15] * s);
        o.h[2 * j + 1] = __float2bfloat16(t[(v[j] >> 4) & 15] * s);
    }
    *reinterpret_cast<uint4*>(&g_W[(size_t)gid * 8]) = o.vec;
}

// ---------------------------------------------------------------------------
// Kernel 2: x convert f32 -> bf16 (values are already bf16-rounded; this is
// a pure narrowing).  8 elements per thread, vectorized.
// ---------------------------------------------------------------------------
__global__ void x_convert_kernel(const float* __restrict__ xf) {
    size_t gid = (size_t)blockIdx.x * blockDim.x + threadIdx.x;  // 4,194,304
    const float4* src = reinterpret_cast<const float4*>(xf) + gid * 2;
    float4 a = src[0];
    float4 b = src[1];
    union { __nv_bfloat16 h[8]; uint4 vec; } o;
    o.h[0] = __float2bfloat16(a.x); o.h[1] = __float2bfloat16(a.y);
    o.h[2] = __float2bfloat16(a.z); o.h[3] = __float2bfloat16(a.w);
    o.h[4] = __float2bfloat16(b.x); o.h[5] = __float2bfloat16(b.y);
    o.h[6] = __float2bfloat16(b.z); o.h[7] = __float2bfloat16(b.w);
    *reinterpret_cast<uint4*>(&g_X[gid * 8]) = o.vec;
}

// ---------------------------------------------------------------------------
// Kernel 3: bf16 GEMM  out[t,o] = sum_k x[t,k] * W[o,k]   (f32 output)
// CTA tile 128x128x32, 8 warps (4M x 2N), warp tile 32x64.
// mma.sync.m16n8k16.row.col, f32 accum, cp.async double buffering.
// ---------------------------------------------------------------------------
#define BM 128
#define BN 128
#define BK 32
#define KS (BK + 8)   // +8 elem pad: conflict-free 32-bit fragment loads

__device__ __forceinline__ void issue_tile(const __nv_bfloat16* __restrict__ gA_base,
                                           const __nv_bfloat16* __restrict__ gB_base,
                                           int k0,
                                           __nv_bfloat16 (*As)[KS],
                                           __nv_bfloat16 (*Bs)[KS],
                                           int tid) {
#pragma unroll
    for (int r = 0; r < 2; ++r) {
        int idx = tid + r * 256;        // 512 16B chunks per operand
        int row = idx >> 2;
        int ch  = idx & 3;
        const __nv_bfloat16* gA = gA_base + (size_t)row * IN_F + k0 + ch * 8;
        uint32_t sA = (uint32_t)__cvta_generic_to_shared(&As[row][ch * 8]);
        asm volatile("cp.async.cg.shared.global [%0], [%1], 16;\n" :: "r"(sA), "l"(gA));
        const __nv_bfloat16* gB = gB_base + (size_t)row * IN_F + k0 + ch * 8;
        uint32_t sB = (uint32_t)__cvta_generic_to_shared(&Bs[row][ch * 8]);
        asm volatile("cp.async.cg.shared.global [%0], [%1], 16;\n" :: "r"(sB), "l"(gB));
    }
    asm volatile("cp.async.commit_group;\n");
}

__global__ __launch_bounds__(256) void nf4_gemm_kernel(float* __restrict__ O) {
    __shared__ __align__(16) __nv_bfloat16 As[2][BM][KS];
    __shared__ __align__(16) __nv_bfloat16 Bs[2][BN][KS];

    const int tid  = threadIdx.x;
    const int warp = tid >> 5;
    const int lane = tid & 31;
    const int wm   = warp >> 1;          // 0..3  (M direction)
    const int wn   = warp & 1;           // 0..1  (N direction)
    const int grp  = lane >> 2;          // 0..7
    const int tq   = lane & 3;           // 0..3

    const int m0 = blockIdx.y * BM;
    const int n0 = blockIdx.x * BN;

    const __nv_bfloat16* gA_base = g_X + (size_t)m0 * IN_F;
    const __nv_bfloat16* gB_base = g_W + (size_t)n0 * IN_F;

    float acc[2][8][4];
#pragma unroll
    for (int mi = 0; mi < 2; ++mi)
#pragma unroll
        for (int ni = 0; ni < 8; ++ni)
#pragma unroll
            for (int c = 0; c < 4; ++c) acc[mi][ni][c] = 0.f;

    issue_tile(gA_base, gB_base, 0, As[0], Bs[0], tid);

    const int NT = IN_F / BK;  // 128
    for (int kt = 0; kt < NT; ++kt) {
        const int buf = kt & 1;
        if (kt + 1 < NT) {
            issue_tile(gA_base, gB_base, (kt + 1) * BK, As[buf ^ 1], Bs[buf ^ 1], tid);
            asm volatile("cp.async.wait_group 1;\n");
        } else {
            asm volatile("cp.async.wait_group 0;\n");
        }
        __syncthreads();

#pragma unroll
        for (int kk = 0; kk < 2; ++kk) {
            const int kb = kk * 16 + tq * 2;
            uint32_t a[2][4];
#pragma unroll
            for (int mi = 0; mi < 2; ++mi) {
                const int row0 = wm * 32 + mi * 16 + grp;
                a[mi][0] = *reinterpret_cast<const uint32_t*>(&As[buf][row0][kb]);
                a[mi][1] = *reinterpret_cast<const uint32_t*>(&As[buf][row0 + 8][kb]);
                a[mi][2] = *reinterpret_cast<const uint32_t*>(&As[buf][row0][kb + 8]);
                a[mi][3] = *reinterpret_cast<const uint32_t*>(&As[buf][row0 + 8][kb + 8]);
            }
#pragma unroll
            for (int ni = 0; ni < 8; ++ni) {
                const int col = wn * 64 + ni * 8 + grp;
                uint32_t b0 = *reinterpret_cast<const uint32_t*>(&Bs[buf][col][kb]);
                uint32_t b1 = *reinterpret_cast<const uint32_t*>(&Bs[buf][col][kb + 8]);
#pragma unroll
                for (int mi = 0; mi < 2; ++mi) {
                    asm volatile(
                        "mma.sync.aligned.m16n8k16.row.col.f32.bf16.bf16.f32 "
                        "{%0,%1,%2,%3}, {%4,%5,%6,%7}, {%8,%9}, {%0,%1,%2,%3};\n"
                        : "+f"(acc[mi][ni][0]), "+f"(acc[mi][ni][1]),
                          "+f"(acc[mi][ni][2]), "+f"(acc[mi][ni][3])
                        : "r"(a[mi][0]), "r"(a[mi][1]), "r"(a[mi][2]), "r"(a[mi][3]),
                          "r"(b0), "r"(b1));
                }
            }
        }
        __syncthreads();
    }

    // Epilogue: round f32 accum to bf16 (matching reference's bf16 output),
    // widen back to f32 and store f32 (harness stores "bf16" tensors as f32).
#pragma unroll
    for (int mi = 0; mi < 2; ++mi) {
        const int row0 = m0 + wm * 32 + mi * 16 + grp;
#pragma unroll
        for (int ni = 0; ni < 8; ++ni) {
            const int col = n0 + wn * 64 + ni * 8 + tq * 2;
            float2 v01, v23;
            v01.x = __bfloat162float(__float2bfloat16(acc[mi][ni][0]));
            v01.y = __bfloat162float(__float2bfloat16(acc[mi][ni][1]));
            v23.x = __bfloat162float(__float2bfloat16(acc[mi][ni][2]));
            v23.y = __bfloat162float(__float2bfloat16(acc[mi][ni][3]));
            *reinterpret_cast<float2*>(&O[(size_t)row0 * OUT_F + col])       = v01;
            *reinterpret_cast<float2*>(&O[(size_t)(row0 + 8) * OUT_F + col]) = v23;
        }
    }
}

// ---------------------------------------------------------------------------
// Bind inputs by ELEMENT COUNT (validated in R7):
//   x: 33,554,432 (f32, bf16-valued)  packed: 8,388,608 (int32, one byte each)
//   scales: 262,144 (f32)             table: 16 (f32)
// Output: 33,554,432 f32 (bf16-valued, widened).
// ---------------------------------------------------------------------------
extern "C" void kernel_launch(void* const* d_in, const int* in_sizes, int n_in,
                              void* d_out, int out_size) {
    const float* x      = nullptr;
    const int*   packed = nullptr;
    const float* scales = nullptr;
    const float* table  = nullptr;

    for (int i = 0; i < n_in; ++i) {
        long n = in_sizes[i];
        if      (n == (long)TOKENS * IN_F)        x      = (const float*)d_in[i];
        else if (n == (long)OUT_F * IN_F / 2)     packed = (const int*)d_in[i];
        else if (n == (long)OUT_F * IN_F / 64)    scales = (const float*)d_in[i];
        else if (n == 16)                         table  = (const float*)d_in[i];
    }

    float* out = (float*)d_out;

    const int n_packed = OUT_F * IN_F / 2;                      // 8,388,608
    nf4_dequant_kernel<<<n_packed / 4 / 256, 256>>>(packed, scales, table);

    const long n_x = (long)TOKENS * IN_F;                       // 33,554,432
    x_convert_kernel<<<(int)(n_x / 8 / 256), 256>>>(x);

    dim3 grid(OUT_F / BN, TOKENS / BM);                         // (32, 64)
    nf4_gemm_kernel<<<grid, 256>>>(out);
}

// round 10
// speedup vs baseline: 1.4141x; 1.4141x over previous
#include <cuda_runtime.h>
#include <cuda_bf16.h>
#include <cstdint>

#define OUT_F 4096
#define IN_F  4096
#define TOKENS 8192

// Static device scratch: dequantized W (32 MB bf16) + x narrowed to bf16 (64 MB)
__device__ __align__(16) __nv_bfloat16 g_W[(size_t)OUT_F * IN_F];
__device__ __align__(16) __nv_bfloat16 g_X[(size_t)TOKENS * IN_F];

// ---------------------------------------------------------------------------
// Kernel 1: NF4 dequant -> bf16 (validated byte-level in R7, passing in R8).
// ---------------------------------------------------------------------------
__global__ void nf4_dequant_kernel(const int* __restrict__ pw,
                                   const float* __restrict__ scales,
                                   const float* __restrict__ table) {
    __shared__ float t[16];
    if (threadIdx.x < 16) t[threadIdx.x] = table[threadIdx.x];
    __syncthreads();

    int gid = blockIdx.x * blockDim.x + threadIdx.x;
    int4 p = reinterpret_cast<const int4*>(pw)[gid];
    float s = scales[gid >> 3];

    int v[4] = {p.x, p.y, p.z, p.w};
    union { __nv_bfloat16 h[8]; uint4 vec; } o;
#pragma unroll
    for (int j = 0; j < 4; ++j) {
        o.h[2 * j]     = __float2bfloat16(t[v[j] & 15] * s);
        o.h[2 * j + 1] = __float2bfloat16(t[(v[j] >> 4) & 15] * s);
    }
    *reinterpret_cast<uint4*>(&g_W[(size_t)gid * 8]) = o.vec;
}

// ---------------------------------------------------------------------------
// Kernel 2: x narrow f32 -> bf16 (values already bf16-rounded).
// ---------------------------------------------------------------------------
__global__ void x_convert_kernel(const float* __restrict__ xf) {
    size_t gid = (size_t)blockIdx.x * blockDim.x + threadIdx.x;
    const float4* src = reinterpret_cast<const float4*>(xf) + gid * 2;
    float4 a = src[0];
    float4 b = src[1];
    union { __nv_bfloat16 h[8]; uint4 vec; } o;
    o.h[0] = __float2bfloat16(a.x); o.h[1] = __float2bfloat16(a.y);
    o.h[2] = __float2bfloat16(a.z); o.h[3] = __float2bfloat16(a.w);
    o.h[4] = __float2bfloat16(b.x); o.h[5] = __float2bfloat16(b.y);
    o.h[6] = __float2bfloat16(b.z); o.h[7] = __float2bfloat16(b.w);
    *reinterpret_cast<uint4*>(&g_X[gid * 8]) = o.vec;
}

// ---------------------------------------------------------------------------
// Kernel 3: bf16 GEMM via mma.sync, 3-stage cp.async, ldmatrix fragments.
// CTA 128(M) x 256(N) x 64(K). 8 warps = 2(M) x 4(N); warp tile 64x64.
// Swizzled smem: 128B rows of 8x16B chunks, chunk ^= (row & 7).
// ---------------------------------------------------------------------------
#define BM 128
#define BN 256
#define BK 64
#define STAGES 3
#define NT (IN_F / BK)                       // 64
#define A_BYTES (BM * BK * 2)                // 16384
#define B_BYTES (BN * BK * 2)                // 32768
#define STAGE_BYTES (A_BYTES + B_BYTES)      // 49152
#define DYN_SMEM (STAGES * STAGE_BYTES)      // 147456

__device__ __forceinline__ uint32_t swz(uint32_t row, uint32_t chunk) {
    return row * 128u + ((chunk ^ (row & 7u)) * 16u);
}
__device__ __forceinline__ void cpa16(uint32_t dst, const void* src) {
    asm volatile("cp.async.cg.shared.global [%0], [%1], 16;\n" :: "r"(dst), "l"(src));
}
__device__ __forceinline__ void ldsm_x4(uint32_t& r0, uint32_t& r1,
                                        uint32_t& r2, uint32_t& r3, uint32_t addr) {
    asm volatile("ldmatrix.sync.aligned.m8n8.x4.shared.b16 {%0,%1,%2,%3}, [%4];\n"
                 : "=r"(r0), "=r"(r1), "=r"(r2), "=r"(r3) : "r"(addr));
}

__device__ __forceinline__ void issue_stage(const __nv_bfloat16* __restrict__ gA,
                                            const __nv_bfloat16* __restrict__ gB,
                                            int kc, uint32_t aB, uint32_t bB, int tid) {
    // A: 1024 16B chunks; 4 per thread
#pragma unroll
    for (int i = 0; i < 4; ++i) {
        int idx = tid + i * 256;
        uint32_t row = idx >> 3, c = idx & 7;
        cpa16(aB + swz(row, c), gA + (size_t)row * IN_F + kc + c * 8);
    }
    // B: 2048 chunks; 8 per thread
#pragma unroll
    for (int i = 0; i < 8; ++i) {
        int idx = tid + i * 256;
        uint32_t row = idx >> 3, c = idx & 7;
        cpa16(bB + swz(row, c), gB + (size_t)row * IN_F + kc + c * 8);
    }
    asm volatile("cp.async.commit_group;\n");
}

__global__ __launch_bounds__(256, 1) void mma_gemm_kernel(float* __restrict__ O) {
    extern __shared__ __align__(1024) char dyn[];
    const uint32_t base = (uint32_t)__cvta_generic_to_shared(dyn);

    const int tid  = threadIdx.x;
    const int warp = tid >> 5;
    const int lane = tid & 31;
    const int wm   = warp >> 2;            // 0..1  (M)
    const int wn   = warp & 3;             // 0..3  (N)

    const int n0 = (blockIdx.x & 15) * BN;
    const int m0 = (blockIdx.x >> 4) * BM;

    const __nv_bfloat16* gA = g_X + (size_t)m0 * IN_F;
    const __nv_bfloat16* gB = g_W + (size_t)n0 * IN_F;

    // ldmatrix lane addressing (precomputed pieces)
    const uint32_t a_row = wm * 64 + (lane & 15);        // + mi*16
    const uint32_t a_chp = (lane >> 4);                  // chunk += ks*2 + this
    const uint32_t b_row = wn * 64 + ((lane >> 4) & 1) * 8 + (lane & 7);  // + p*16
    const uint32_t b_chp = (lane >> 3) & 1;

    float acc[4][8][4];
#pragma unroll
    for (int mi = 0; mi < 4; ++mi)
#pragma unroll
        for (int ni = 0; ni < 8; ++ni)
#pragma unroll
            for (int c = 0; c < 4; ++c) acc[mi][ni][c] = 0.f;

    // prologue: stages 0,1
    issue_stage(gA, gB, 0, base, base + A_BYTES, tid);
    issue_stage(gA, gB, BK, base + STAGE_BYTES, base + STAGE_BYTES + A_BYTES, tid);

    uint32_t fa[2][4][4], fb[2][8][2];

    for (int kt = 0; kt < NT; ++kt) {
        if (kt < NT - 1) { asm volatile("cp.async.wait_group 1;\n"); }
        else             { asm volatile("cp.async.wait_group 0;\n"); }
        __syncthreads();

        const int st = kt % STAGES;
        const uint32_t aB = base + st * STAGE_BYTES;
        const uint32_t bB = aB + A_BYTES;

        if (kt + 2 < NT) {
            const int st2 = (kt + 2) % STAGES;
            issue_stage(gA, gB, (kt + 2) * BK,
                        base + st2 * STAGE_BYTES,
                        base + st2 * STAGE_BYTES + A_BYTES, tid);
        }

        // load fragments for ks=0 into buffer 0
#pragma unroll
        for (int mi = 0; mi < 4; ++mi) {
            uint32_t row = a_row + mi * 16;
            ldsm_x4(fa[0][mi][0], fa[0][mi][1], fa[0][mi][2], fa[0][mi][3],
                    aB + swz(row, a_chp));
        }
#pragma unroll
        for (int p = 0; p < 4; ++p) {
            uint32_t row = b_row + p * 16;
            ldsm_x4(fb[0][2 * p][0], fb[0][2 * p][1],
                    fb[0][2 * p + 1][0], fb[0][2 * p + 1][1],
                    bB + swz(row, b_chp));
        }

#pragma unroll
        for (int ks = 0; ks < 4; ++ks) {
            const int cur = ks & 1, nxt = cur ^ 1;
            if (ks < 3) {
                const uint32_t kch = (ks + 1) * 2;
#pragma unroll
                for (int mi = 0; mi < 4; ++mi) {
                    uint32_t row = a_row + mi * 16;
                    ldsm_x4(fa[nxt][mi][0], fa[nxt][mi][1],
                            fa[nxt][mi][2], fa[nxt][mi][3],
                            aB + swz(row, kch + a_chp));
                }
#pragma unroll
                for (int p = 0; p < 4; ++p) {
                    uint32_t row = b_row + p * 16;
                    ldsm_x4(fb[nxt][2 * p][0], fb[nxt][2 * p][1],
                            fb[nxt][2 * p + 1][0], fb[nxt][2 * p + 1][1],
                            bB + swz(row, kch + b_chp));
                }
            }
#pragma unroll
            for (int ni = 0; ni < 8; ++ni)
#pragma unroll
                for (int mi = 0; mi < 4; ++mi) {
                    asm volatile(
                        "mma.sync.aligned.m16n8k16.row.col.f32.bf16.bf16.f32 "
                        "{%0,%1,%2,%3}, {%4,%5,%6,%7}, {%8,%9}, {%0,%1,%2,%3};\n"
                        : "+f"(acc[mi][ni][0]), "+f"(acc[mi][ni][1]),
                          "+f"(acc[mi][ni][2]), "+f"(acc[mi][ni][3])
                        : "r"(fa[cur][mi][0]), "r"(fa[cur][mi][1]),
                          "r"(fa[cur][mi][2]), "r"(fa[cur][mi][3]),
                          "r"(fb[cur][ni][0]), "r"(fb[cur][ni][1]));
                }
        }
        __syncthreads();
    }

    // Epilogue: bf16-round, widen to f32, float2 stores
    const int grp = lane >> 2;       // 0..7
    const int tq  = lane & 3;        // 0..3
#pragma unroll
    for (int mi = 0; mi < 4; ++mi) {
        const int row0 = m0 + wm * 64 + mi * 16 + grp;
#pragma unroll
        for (int ni = 0; ni < 8; ++ni) {
            const int col = n0 + wn * 64 + ni * 8 + tq * 2;
            float2 v01, v23;
            v01.x = __bfloat162float(__float2bfloat16(acc[mi][ni][0]));
            v01.y = __bfloat162float(__float2bfloat16(acc[mi][ni][1]));
            v23.x = __bfloat162float(__float2bfloat16(acc[mi][ni][2]));
            v23.y = __bfloat162float(__float2bfloat16(acc[mi][ni][3]));
            *reinterpret_cast<float2*>(&O[(size_t)row0 * OUT_F + col])       = v01;
            *reinterpret_cast<float2*>(&O[(size_t)(row0 + 8) * OUT_F + col]) = v23;
        }
    }
}

// ---------------------------------------------------------------------------
extern "C" void kernel_launch(void* const* d_in, const int* in_sizes, int n_in,
                              void* d_out, int out_size) {
    const float* x      = nullptr;
    const int*   packed = nullptr;
    const float* scales = nullptr;
    const float* table  = nullptr;

    for (int i = 0; i < n_in; ++i) {
        long n = in_sizes[i];
        if      (n == (long)TOKENS * IN_F)        x      = (const float*)d_in[i];
        else if (n == (long)OUT_F * IN_F / 2)     packed = (const int*)d_in[i];
        else if (n == (long)OUT_F * IN_F / 64)    scales = (const float*)d_in[i];
        else if (n == 16)                         table  = (const float*)d_in[i];
    }

    float* out = (float*)d_out;

    const int n_packed = OUT_F * IN_F / 2;
    nf4_dequant_kernel<<<n_packed / 4 / 256, 256>>>(packed, scales, table);

    const long n_x = (long)TOKENS * IN_F;
    x_convert_kernel<<<(int)(n_x / 8 / 256), 256>>>(x);

    static bool attr_set = false;
    if (!attr_set) {
        cudaFuncSetAttribute(mma_gemm_kernel,
                             cudaFuncAttributeMaxDynamicSharedMemorySize, DYN_SMEM);
        attr_set = true;
    }
    // grid: 64 M-blocks x 16 N-blocks, N fastest (x row-block L2 reuse)
    mma_gemm_kernel<<<(TOKENS / BM) * (OUT_F / BN), 256, DYN_SMEM>>>(out);
}

// round 11
// speedup vs baseline: 1.4537x; 1.0280x over previous
#include <cuda_runtime.h>
#include <cuda_bf16.h>
#include <cstdint>

#define OUT_F 4096
#define IN_F  4096
#define TOKENS 8192

// Static device scratch: dequantized W (32 MB bf16) + x narrowed to bf16 (64 MB)
__device__ __align__(16) __nv_bfloat16 g_W[(size_t)OUT_F * IN_F];
__device__ __align__(16) __nv_bfloat16 g_X[(size_t)TOKENS * IN_F];

// ---------------------------------------------------------------------------
// Kernel 1: NF4 dequant -> bf16 (validated byte-level in R7, passing since R8).
// ---------------------------------------------------------------------------
__global__ void nf4_dequant_kernel(const int* __restrict__ pw,
                                   const float* __restrict__ scales,
                                   const float* __restrict__ table) {
    __shared__ float t[16];
    if (threadIdx.x < 16) t[threadIdx.x] = table[threadIdx.x];
    __syncthreads();

    int gid = blockIdx.x * blockDim.x + threadIdx.x;
    int4 p = reinterpret_cast<const int4*>(pw)[gid];
    float s = scales[gid >> 3];

    int v[4] = {p.x, p.y, p.z, p.w};
    union { __nv_bfloat16 h[8]; uint4 vec; } o;
#pragma unroll
    for (int j = 0; j < 4; ++j) {
        o.h[2 * j]     = __float2bfloat16(t[v[j] & 15] * s);
        o.h[2 * j + 1] = __float2bfloat16(t[(v[j] >> 4) & 15] * s);
    }
    *reinterpret_cast<uint4*>(&g_W[(size_t)gid * 8]) = o.vec;
}

// ---------------------------------------------------------------------------
// Kernel 2: x narrow f32 -> bf16 (values already bf16-rounded).
// ---------------------------------------------------------------------------
__global__ void x_convert_kernel(const float* __restrict__ xf) {
    size_t gid = (size_t)blockIdx.x * blockDim.x + threadIdx.x;
    const float4* src = reinterpret_cast<const float4*>(xf) + gid * 2;
    float4 a = src[0];
    float4 b = src[1];
    union { __nv_bfloat16 h[8]; uint4 vec; } o;
    o.h[0] = __float2bfloat16(a.x); o.h[1] = __float2bfloat16(a.y);
    o.h[2] = __float2bfloat16(a.z); o.h[3] = __float2bfloat16(a.w);
    o.h[4] = __float2bfloat16(b.x); o.h[5] = __float2bfloat16(b.y);
    o.h[6] = __float2bfloat16(b.z); o.h[7] = __float2bfloat16(b.w);
    *reinterpret_cast<uint4*>(&g_X[gid * 8]) = o.vec;
}

// ---------------------------------------------------------------------------
// Kernel 3: bf16 GEMM via mma.sync, 4-stage cp.async, ldmatrix fragments.
// CTA 128(M) x 256(N) x 64(K). 8 warps = 2(M) x 4(N); warp tile 64x64.
// Swizzled smem: 128B rows of 8x16B chunks, chunk ^= (row & 7).
// ONE __syncthreads per K-tile (trailing barrier proven redundant: the
// top-of-loop wait+sync at iter kt+1 orders all stage-kt reads before any
// prefetch that could overwrite that slot).
// ---------------------------------------------------------------------------
#define BM 128
#define BN 256
#define BK 64
#define STAGES 4
#define NT (IN_F / BK)                       // 64
#define A_BYTES (BM * BK * 2)                // 16384
#define B_BYTES (BN * BK * 2)                // 32768
#define STAGE_BYTES (A_BYTES + B_BYTES)      // 49152
#define DYN_SMEM (STAGES * STAGE_BYTES)      // 196608

__device__ __forceinline__ uint32_t swz(uint32_t row, uint32_t chunk) {
    return row * 128u + ((chunk ^ (row & 7u)) * 16u);
}
__device__ __forceinline__ void cpa16(uint32_t dst, const void* src) {
    asm volatile("cp.async.cg.shared.global [%0], [%1], 16;\n" :: "r"(dst), "l"(src));
}
__device__ __forceinline__ void ldsm_x4(uint32_t& r0, uint32_t& r1,
                                        uint32_t& r2, uint32_t& r3, uint32_t addr) {
    asm volatile("ldmatrix.sync.aligned.m8n8.x4.shared.b16 {%0,%1,%2,%3}, [%4];\n"
                 : "=r"(r0), "=r"(r1), "=r"(r2), "=r"(r3) : "r"(addr));
}

__device__ __forceinline__ void issue_stage(const __nv_bfloat16* __restrict__ gA,
                                            const __nv_bfloat16* __restrict__ gB,
                                            int kc, uint32_t aB, uint32_t bB, int tid) {
    // A: 1024 16B chunks; 4 per thread
#pragma unroll
    for (int i = 0; i < 4; ++i) {
        int idx = tid + i * 256;
        uint32_t row = idx >> 3, c = idx & 7;
        cpa16(aB + swz(row, c), gA + (size_t)row * IN_F + kc + c * 8);
    }
    // B: 2048 chunks; 8 per thread
#pragma unroll
    for (int i = 0; i < 8; ++i) {
        int idx = tid + i * 256;
        uint32_t row = idx >> 3, c = idx & 7;
        cpa16(bB + swz(row, c), gB + (size_t)row * IN_F + kc + c * 8);
    }
    asm volatile("cp.async.commit_group;\n");
}

__global__ __launch_bounds__(256, 1) void mma_gemm_kernel(float* __restrict__ O) {
    extern __shared__ __align__(1024) char dyn[];
    const uint32_t base = (uint32_t)__cvta_generic_to_shared(dyn);

    const int tid  = threadIdx.x;
    const int warp = tid >> 5;
    const int lane = tid & 31;
    const int wm   = warp >> 2;            // 0..1  (M)
    const int wn   = warp & 3;             // 0..3  (N)

    const int n0 = (blockIdx.x & 15) * BN;
    const int m0 = (blockIdx.x >> 4) * BM;

    const __nv_bfloat16* gA = g_X + (size_t)m0 * IN_F;
    const __nv_bfloat16* gB = g_W + (size_t)n0 * IN_F;

    // ldmatrix lane addressing (precomputed pieces)
    const uint32_t a_row = wm * 64 + (lane & 15);        // + mi*16
    const uint32_t a_chp = (lane >> 4);                  // chunk += ks*2 + this
    const uint32_t b_row = wn * 64 + ((lane >> 4) & 1) * 8 + (lane & 7);  // + p*16
    const uint32_t b_chp = (lane >> 3) & 1;

    float acc[4][8][4];
#pragma unroll
    for (int mi = 0; mi < 4; ++mi)
#pragma unroll
        for (int ni = 0; ni < 8; ++ni)
#pragma unroll
            for (int c = 0; c < 4; ++c) acc[mi][ni][c] = 0.f;

    // prologue: stages 0,1,2 in flight (prefetch distance 3)
    issue_stage(gA, gB, 0,      base,                   base + A_BYTES, tid);
    issue_stage(gA, gB, BK,     base + STAGE_BYTES,     base + STAGE_BYTES + A_BYTES, tid);
    issue_stage(gA, gB, 2 * BK, base + 2 * STAGE_BYTES, base + 2 * STAGE_BYTES + A_BYTES, tid);

    uint32_t fa[2][4][4], fb[2][8][2];

    for (int kt = 0; kt < NT; ++kt) {
        // tail-exact wait: pending groups after this wait = remaining prefetches
        if (kt < NT - 2)      { asm volatile("cp.async.wait_group 2;\n"); }
        else if (kt == NT - 2){ asm volatile("cp.async.wait_group 1;\n"); }
        else                  { asm volatile("cp.async.wait_group 0;\n"); }
        __syncthreads();   // stage kt%4 ready for ALL threads; also orders
                           // everyone past reads of stage (kt-1): prefetch below
                           // targeting (kt+3)%4 cannot race readers of (kt-1)%4.

        const int st = kt & 3;
        const uint32_t aB = base + st * STAGE_BYTES;
        const uint32_t bB = aB + A_BYTES;

        if (kt + 3 < NT) {
            const int st2 = (kt + 3) & 3;
            issue_stage(gA, gB, (kt + 3) * BK,
                        base + st2 * STAGE_BYTES,
                        base + st2 * STAGE_BYTES + A_BYTES, tid);
        }

        // load fragments for ks=0 into buffer 0
#pragma unroll
        for (int mi = 0; mi < 4; ++mi) {
            uint32_t row = a_row + mi * 16;
            ldsm_x4(fa[0][mi][0], fa[0][mi][1], fa[0][mi][2], fa[0][mi][3],
                    aB + swz(row, a_chp));
        }
#pragma unroll
        for (int p = 0; p < 4; ++p) {
            uint32_t row = b_row + p * 16;
            ldsm_x4(fb[0][2 * p][0], fb[0][2 * p][1],
                    fb[0][2 * p + 1][0], fb[0][2 * p + 1][1],
                    bB + swz(row, b_chp));
        }

#pragma unroll
        for (int ks = 0; ks < 4; ++ks) {
            const int cur = ks & 1, nxt = cur ^ 1;
            if (ks < 3) {
                const uint32_t kch = (ks + 1) * 2;
#pragma unroll
                for (int mi = 0; mi < 4; ++mi) {
                    uint32_t row = a_row + mi * 16;
                    ldsm_x4(fa[nxt][mi][0], fa[nxt][mi][1],
                            fa[nxt][mi][2], fa[nxt][mi][3],
                            aB + swz(row, kch + a_chp));
                }
#pragma unroll
                for (int p = 0; p < 4; ++p) {
                    uint32_t row = b_row + p * 16;
                    ldsm_x4(fb[nxt][2 * p][0], fb[nxt][2 * p][1],
                            fb[nxt][2 * p + 1][0], fb[nxt][2 * p + 1][1],
                            bB + swz(row, kch + b_chp));
                }
            }
#pragma unroll
            for (int ni = 0; ni < 8; ++ni)
#pragma unroll
                for (int mi = 0; mi < 4; ++mi) {
                    asm volatile(
                        "mma.sync.aligned.m16n8k16.row.col.f32.bf16.bf16.f32 "
                        "{%0,%1,%2,%3}, {%4,%5,%6,%7}, {%8,%9}, {%0,%1,%2,%3};\n"
                        : "+f"(acc[mi][ni][0]), "+f"(acc[mi][ni][1]),
                          "+f"(acc[mi][ni][2]), "+f"(acc[mi][ni][3])
                        : "r"(fa[cur][mi][0]), "r"(fa[cur][mi][1]),
                          "r"(fa[cur][mi][2]), "r"(fa[cur][mi][3]),
                          "r"(fb[cur][ni][0]), "r"(fb[cur][ni][1]));
                }
        }
        // no trailing barrier (see header comment)
    }

    // Epilogue: bf16-round, widen to f32, float2 stores
    const int grp = lane >> 2;       // 0..7
    const int tq  = lane & 3;        // 0..3
#pragma unroll
    for (int mi = 0; mi < 4; ++mi) {
        const int row0 = m0 + wm * 64 + mi * 16 + grp;
#pragma unroll
        for (int ni = 0; ni < 8; ++ni) {
            const int col = n0 + wn * 64 + ni * 8 + tq * 2;
            float2 v01, v23;
            v01.x = __bfloat162float(__float2bfloat16(acc[mi][ni][0]));
            v01.y = __bfloat162float(__float2bfloat16(acc[mi][ni][1]));
            v23.x = __bfloat162float(__float2bfloat16(acc[mi][ni][2]));
            v23.y = __bfloat162float(__float2bfloat16(acc[mi][ni][3]));
            *reinterpret_cast<float2*>(&O[(size_t)row0 * OUT_F + col])       = v01;
            *reinterpret_cast<float2*>(&O[(size_t)(row0 + 8) * OUT_F + col]) = v23;
        }
    }
}

// ---------------------------------------------------------------------------
extern "C" void kernel_launch(void* const* d_in, const int* in_sizes, int n_in,
                              void* d_out, int out_size) {
    const float* x      = nullptr;
    const int*   packed = nullptr;
    const float* scales = nullptr;
    const float* table  = nullptr;

    for (int i = 0; i < n_in; ++i) {
        long n = in_sizes[i];
        if      (n == (long)TOKENS * IN_F)        x      = (const float*)d_in[i];
        else if (n == (long)OUT_F * IN_F / 2)     packed = (const int*)d_in[i];
        else if (n == (long)OUT_F * IN_F / 64)    scales = (const float*)d_in[i];
        else if (n == 16)                         table  = (const float*)d_in[i];
    }

    float* out = (float*)d_out;

    const int n_packed = OUT_F * IN_F / 2;
    nf4_dequant_kernel<<<n_packed / 4 / 256, 256>>>(packed, scales, table);

    const long n_x = (long)TOKENS * IN_F;
    x_convert_kernel<<<(int)(n_x / 8 / 256), 256>>>(x);

    static bool attr_set = false;
    if (!attr_set) {
        cudaFuncSetAttribute(mma_gemm_kernel,
                             cudaFuncAttributeMaxDynamicSharedMemorySize, DYN_SMEM);
        attr_set = true;
    }
    // grid: 64 M-blocks x 16 N-blocks, N fastest (x row-block L2 reuse)
    mma_gemm_kernel<<<(TOKENS / BM) * (OUT_F / BN), 256, DYN_SMEM>>>(out);
}

// round 12
// speedup vs baseline: 1.5150x; 1.0422x over previous
#include <cuda_runtime.h>
#include <cuda_bf16.h>
#include <cstdint>

#define OUT_F 4096
#define IN_F  4096
#define TOKENS 8192

// Static device scratch: dequantized W (32 MB bf16) + x narrowed to bf16 (64 MB)
__device__ __align__(16) __nv_bfloat16 g_W[(size_t)OUT_F * IN_F];
__device__ __align__(16) __nv_bfloat16 g_X[(size_t)TOKENS * IN_F];

// ---------------------------------------------------------------------------
// Kernel 1: NF4 dequant -> bf16 (validated byte-level in R7, passing since R8).
// ---------------------------------------------------------------------------
__global__ void nf4_dequant_kernel(const int* __restrict__ pw,
                                   const float* __restrict__ scales,
                                   const float* __restrict__ table) {
    __shared__ float t[16];
    if (threadIdx.x < 16) t[threadIdx.x] = table[threadIdx.x];
    __syncthreads();

    int gid = blockIdx.x * blockDim.x + threadIdx.x;
    int4 p = reinterpret_cast<const int4*>(pw)[gid];
    float s = scales[gid >> 3];

    int v[4] = {p.x, p.y, p.z, p.w};
    union { __nv_bfloat16 h[8]; uint4 vec; } o;
#pragma unroll
    for (int j = 0; j < 4; ++j) {
        o.h[2 * j]     = __float2bfloat16(t[v[j] & 15] * s);
        o.h[2 * j + 1] = __float2bfloat16(t[(v[j] >> 4) & 15] * s);
    }
    *reinterpret_cast<uint4*>(&g_W[(size_t)gid * 8]) = o.vec;
}

// ---------------------------------------------------------------------------
// Kernel 2: x narrow f32 -> bf16 (values already bf16-rounded).
// ---------------------------------------------------------------------------
__global__ void x_convert_kernel(const float* __restrict__ xf) {
    size_t gid = (size_t)blockIdx.x * blockDim.x + threadIdx.x;
    const float4* src = reinterpret_cast<const float4*>(xf) + gid * 2;
    float4 a = src[0];
    float4 b = src[1];
    union { __nv_bfloat16 h[8]; uint4 vec; } o;
    o.h[0] = __float2bfloat16(a.x); o.h[1] = __float2bfloat16(a.y);
    o.h[2] = __float2bfloat16(a.z); o.h[3] = __float2bfloat16(a.w);
    o.h[4] = __float2bfloat16(b.x); o.h[5] = __float2bfloat16(b.y);
    o.h[6] = __float2bfloat16(b.z); o.h[7] = __float2bfloat16(b.w);
    *reinterpret_cast<uint4*>(&g_X[gid * 8]) = o.vec;
}

// ---------------------------------------------------------------------------
// Kernel 3: bf16 GEMM via mma.sync, 3-stage cp.async, ldmatrix fragments.
// CTA 128(M) x 128(N) x 64(K), 128 threads = 4 warps (2M x 2N), warp 64x64.
// 96 KB smem/CTA -> TWO CTAs per SM: mutual overlap of prologue/epilogue/
// barrier bubbles that capped R11 at ~77% of the HMMA pipe floor.
// Swizzle: 128B rows of 8x16B chunks, chunk ^= (row & 7).
// ---------------------------------------------------------------------------
#define BM 128
#define BN 128
#define BK 64
#define STAGES 3
#define NT (IN_F / BK)                       // 64
#define A_BYTES (BM * BK * 2)                // 16384
#define B_BYTES (BN * BK * 2)                // 16384
#define STAGE_BYTES (A_BYTES + B_BYTES)      // 32768
#define DYN_SMEM (STAGES * STAGE_BYTES)      // 98304

__device__ __forceinline__ uint32_t swz(uint32_t row, uint32_t chunk) {
    return row * 128u + ((chunk ^ (row & 7u)) * 16u);
}
__device__ __forceinline__ void cpa16(uint32_t dst, const void* src) {
    asm volatile("cp.async.cg.shared.global [%0], [%1], 16;\n" :: "r"(dst), "l"(src));
}
__device__ __forceinline__ void ldsm_x4(uint32_t& r0, uint32_t& r1,
                                        uint32_t& r2, uint32_t& r3, uint32_t addr) {
    asm volatile("ldmatrix.sync.aligned.m8n8.x4.shared.b16 {%0,%1,%2,%3}, [%4];\n"
                 : "=r"(r0), "=r"(r1), "=r"(r2), "=r"(r3) : "r"(addr));
}

__device__ __forceinline__ void issue_stage(const __nv_bfloat16* __restrict__ gA,
                                            const __nv_bfloat16* __restrict__ gB,
                                            int kc, uint32_t aB, uint32_t bB, int tid) {
    // A: 1024 16B chunks; 8 per thread (128 threads)
#pragma unroll
    for (int i = 0; i < 8; ++i) {
        int idx = tid + i * 128;
        uint32_t row = idx >> 3, c = idx & 7;
        cpa16(aB + swz(row, c), gA + (size_t)row * IN_F + kc + c * 8);
    }
    // B: 1024 chunks; 8 per thread
#pragma unroll
    for (int i = 0; i < 8; ++i) {
        int idx = tid + i * 128;
        uint32_t row = idx >> 3, c = idx & 7;
        cpa16(bB + swz(row, c), gB + (size_t)row * IN_F + kc + c * 8);
    }
    asm volatile("cp.async.commit_group;\n");
}

__global__ __launch_bounds__(128, 2) void mma_gemm_kernel(float* __restrict__ O) {
    extern __shared__ __align__(1024) char dyn[];
    const uint32_t base = (uint32_t)__cvta_generic_to_shared(dyn);

    const int tid  = threadIdx.x;
    const int warp = tid >> 5;
    const int lane = tid & 31;
    const int wm   = warp >> 1;            // 0..1  (M)
    const int wn   = warp & 1;             // 0..1  (N)

    const int n0 = (blockIdx.x & 31) * BN;
    const int m0 = (blockIdx.x >> 5) * BM;

    const __nv_bfloat16* gA = g_X + (size_t)m0 * IN_F;
    const __nv_bfloat16* gB = g_W + (size_t)n0 * IN_F;

    // ldmatrix lane addressing (mapping validated since R10)
    const uint32_t a_row = wm * 64 + (lane & 15);        // + mi*16
    const uint32_t a_chp = (lane >> 4);                  // chunk += ks*2 + this
    const uint32_t b_row = wn * 64 + ((lane >> 4) & 1) * 8 + (lane & 7);  // + p*16
    const uint32_t b_chp = (lane >> 3) & 1;

    float acc[4][8][4];
#pragma unroll
    for (int mi = 0; mi < 4; ++mi)
#pragma unroll
        for (int ni = 0; ni < 8; ++ni)
#pragma unroll
            for (int c = 0; c < 4; ++c) acc[mi][ni][c] = 0.f;

    // prologue: stages 0,1 in flight (prefetch distance 2)
    issue_stage(gA, gB, 0,  base,               base + A_BYTES, tid);
    issue_stage(gA, gB, BK, base + STAGE_BYTES, base + STAGE_BYTES + A_BYTES, tid);

    uint32_t fa[2][4][4], fb[2][8][2];

    for (int kt = 0; kt < NT; ++kt) {
        if (kt < NT - 1) { asm volatile("cp.async.wait_group 1;\n"); }
        else             { asm volatile("cp.async.wait_group 0;\n"); }
        __syncthreads();   // stage kt ready for ALL threads; also orders every
                           // thread's reads of stage kt-1 before the prefetch
                           // below that overwrites slot (kt+2)%3 == (kt-1)%3.

        const int st = kt % STAGES;
        const uint32_t aB = base + st * STAGE_BYTES;
        const uint32_t bB = aB + A_BYTES;

        if (kt + 2 < NT) {
            const int st2 = (kt + 2) % STAGES;
            issue_stage(gA, gB, (kt + 2) * BK,
                        base + st2 * STAGE_BYTES,
                        base + st2 * STAGE_BYTES + A_BYTES, tid);
        }

        // fragments for ks=0 into buffer 0
#pragma unroll
        for (int mi = 0; mi < 4; ++mi) {
            uint32_t row = a_row + mi * 16;
            ldsm_x4(fa[0][mi][0], fa[0][mi][1], fa[0][mi][2], fa[0][mi][3],
                    aB + swz(row, a_chp));
        }
#pragma unroll
        for (int p = 0; p < 4; ++p) {
            uint32_t row = b_row + p * 16;
            ldsm_x4(fb[0][2 * p][0], fb[0][2 * p][1],
                    fb[0][2 * p + 1][0], fb[0][2 * p + 1][1],
                    bB + swz(row, b_chp));
        }

#pragma unroll
        for (int ks = 0; ks < 4; ++ks) {
            const int cur = ks & 1, nxt = cur ^ 1;
            if (ks < 3) {
                const uint32_t kch = (ks + 1) * 2;
#pragma unroll
                for (int mi = 0; mi < 4; ++mi) {
                    uint32_t row = a_row + mi * 16;
                    ldsm_x4(fa[nxt][mi][0], fa[nxt][mi][1],
                            fa[nxt][mi][2], fa[nxt][mi][3],
                            aB + swz(row, kch + a_chp));
                }
#pragma unroll
                for (int p = 0; p < 4; ++p) {
                    uint32_t row = b_row + p * 16;
                    ldsm_x4(fb[nxt][2 * p][0], fb[nxt][2 * p][1],
                            fb[nxt][2 * p + 1][0], fb[nxt][2 * p + 1][1],
                            bB + swz(row, kch + b_chp));
                }
            }
#pragma unroll
            for (int ni = 0; ni < 8; ++ni)
#pragma unroll
                for (int mi = 0; mi < 4; ++mi) {
                    asm volatile(
                        "mma.sync.aligned.m16n8k16.row.col.f32.bf16.bf16.f32 "
                        "{%0,%1,%2,%3}, {%4,%5,%6,%7}, {%8,%9}, {%0,%1,%2,%3};\n"
                        : "+f"(acc[mi][ni][0]), "+f"(acc[mi][ni][1]),
                          "+f"(acc[mi][ni][2]), "+f"(acc[mi][ni][3])
                        : "r"(fa[cur][mi][0]), "r"(fa[cur][mi][1]),
                          "r"(fa[cur][mi][2]), "r"(fa[cur][mi][3]),
                          "r"(fb[cur][ni][0]), "r"(fb[cur][ni][1]));
                }
        }
        // no trailing barrier (ordering argument above)
    }

    // Epilogue: bf16-round, widen to f32, float2 stores
    const int grp = lane >> 2;       // 0..7
    const int tq  = lane & 3;        // 0..3
#pragma unroll
    for (int mi = 0; mi < 4; ++mi) {
        const int row0 = m0 + wm * 64 + mi * 16 + grp;
#pragma unroll
        for (int ni = 0; ni < 8; ++ni) {
            const int col = n0 + wn * 64 + ni * 8 + tq * 2;
            float2 v01, v23;
            v01.x = __bfloat162float(__float2bfloat16(acc[mi][ni][0]));
            v01.y = __bfloat162float(__float2bfloat16(acc[mi][ni][1]));
            v23.x = __bfloat162float(__float2bfloat16(acc[mi][ni][2]));
            v23.y = __bfloat162float(__float2bfloat16(acc[mi][ni][3]));
            *reinterpret_cast<float2*>(&O[(size_t)row0 * OUT_F + col])       = v01;
            *reinterpret_cast<float2*>(&O[(size_t)(row0 + 8) * OUT_F + col]) = v23;
        }
    }
}

// ---------------------------------------------------------------------------
extern "C" void kernel_launch(void* const* d_in, const int* in_sizes, int n_in,
                              void* d_out, int out_size) {
    const float* x      = nullptr;
    const int*   packed = nullptr;
    const float* scales = nullptr;
    const float* table  = nullptr;

    for (int i = 0; i < n_in; ++i) {
        long n = in_sizes[i];
        if      (n == (long)TOKENS * IN_F)        x      = (const float*)d_in[i];
        else if (n == (long)OUT_F * IN_F / 2)     packed = (const int*)d_in[i];
        else if (n == (long)OUT_F * IN_F / 64)    scales = (const float*)d_in[i];
        else if (n == 16)                         table  = (const float*)d_in[i];
    }

    float* out = (float*)d_out;

    const int n_packed = OUT_F * IN_F / 2;
    nf4_dequant_kernel<<<n_packed / 4 / 256, 256>>>(packed, scales, table);

    const long n_x = (long)TOKENS * IN_F;
    x_convert_kernel<<<(int)(n_x / 8 / 256), 256>>>(x);

    static bool attr_set = false;
    if (!attr_set) {
        cudaFuncSetAttribute(mma_gemm_kernel,
                             cudaFuncAttributeMaxDynamicSharedMemorySize, DYN_SMEM);
        attr_set = true;
    }
    // grid: 64 M-blocks x 32 N-blocks, N fastest (x row-block L2 reuse)
    mma_gemm_kernel<<<(TOKENS / BM) * (OUT_F / BN), 128, DYN_SMEM>>>(out);
}